// round 6
// baseline (speedup 1.0000x reference)
#include <cuda_runtime.h>
#include <math.h>

// ---------------------------------------------------------------------------
// Problem constants
// ---------------------------------------------------------------------------
#define BATCH 64
#define HDIM  1024
#define EDIM  512
#define VDIM  50000
#define LQ    32
#define LD    400

// Output layout (tuple concat, float32):
// out[B,V], h1[1,B,H], c1, dh, dc, doc_w[B,1,LD]
#define OFF_OUT   0
#define OFF_H1    (3200000)
#define OFF_C1    (OFF_H1 + 65536)
#define OFF_DH    (OFF_C1 + 65536)
#define OFF_DC    (OFF_DH + 65536)
#define OFF_DOCW  (OFF_DC + 65536)

// ---------------------------------------------------------------------------
// Scratch (device globals: no allocations allowed)
// ---------------------------------------------------------------------------
__device__ float g_qpart [BATCH * HDIM];          // h_last @ W_qa_h^T
__device__ float g_partq [LQ * BATCH * 8];        // query score partials (8 n-blocks)
__device__ float g_wq    [BATCH * LQ];            // query attn weights
__device__ float g_docq  [BATCH * 2 * HDIM];      // [h_last | q_ctx]
__device__ float g_dqpart[BATCH * HDIM];          // doc_query @ W_da_h^T
__device__ float g_partd [LD * BATCH * 8];        // doc score partials
__device__ float g_wd    [BATCH * LD];            // doc attn weights
__device__ float g_xcat  [BATCH * 1536];          // [embedded(512) | doc_ctx(1024)]
__device__ float g_xout  [BATCH * 2048];          // [h1 | doc_ctx]
__device__ float g_gates [BATCH * 4096];
__device__ float g_dgates[BATCH * 4096];

// ---------------------------------------------------------------------------
// Generic NT SGEMM: C[M,N] = A[M,K] * W[N,K]^T  (both K-contiguous)
// FUSED=false : C = acc (+bias1[n]) (+bias2[n]) (+= C if accC)
// FUSED=true  : per-row partial of  sum_n tanh(acc + qadd[b,n] + bias1[n])*v[n]
//               written deterministically to part[m*gridDim.x + blockIdx.x]
//               (b = m % 64; requires N-tiles exactly covering N=1024, BN/TN==16)
// ---------------------------------------------------------------------------
template<int BM, int BN, int BK, int TM, int TN, bool FUSED>
__global__ __launch_bounds__((BM/TM)*(BN/TN))
void gemm_nt(const float* __restrict__ A, int lda,
             const float* __restrict__ W, int ldw,
             float* __restrict__ C, int ldc,
             int M, int N, int K,
             const float* __restrict__ bias1,
             const float* __restrict__ bias2,
             int accC,
             const float* __restrict__ qadd,
             const float* __restrict__ vvec,
             float* __restrict__ part)
{
    constexpr int NTH = (BM / TM) * (BN / TN);
    constexpr int TX  = BN / TN;
    __shared__ float As[BK][BM];
    __shared__ float Bs[BK][BN];

    const int tid = threadIdx.x;
    const int tx  = tid % TX;
    const int ty  = tid / TX;
    const int m0  = blockIdx.y * BM;
    const int n0  = blockIdx.x * BN;

    float acc[TM][TN];
#pragma unroll
    for (int i = 0; i < TM; i++)
#pragma unroll
        for (int j = 0; j < TN; j++) acc[i][j] = 0.f;

    constexpr int LA = (BM * BK / 4) / NTH;
    constexpr int LB = (BN * BK / 4) / NTH;

    for (int k0 = 0; k0 < K; k0 += BK) {
#pragma unroll
        for (int i = 0; i < LA; i++) {
            int s   = i * NTH + tid;
            int row = s / (BK / 4);
            int kq  = s % (BK / 4);
            float4 a;
            if (m0 + row < M)
                a = *reinterpret_cast<const float4*>(A + (size_t)(m0 + row) * lda + k0 + kq * 4);
            else
                a = make_float4(0.f, 0.f, 0.f, 0.f);
            As[kq * 4 + 0][row] = a.x; As[kq * 4 + 1][row] = a.y;
            As[kq * 4 + 2][row] = a.z; As[kq * 4 + 3][row] = a.w;
        }
#pragma unroll
        for (int i = 0; i < LB; i++) {
            int s   = i * NTH + tid;
            int row = s / (BK / 4);
            int kq  = s % (BK / 4);
            float4 b;
            if (n0 + row < N)
                b = *reinterpret_cast<const float4*>(W + (size_t)(n0 + row) * ldw + k0 + kq * 4);
            else
                b = make_float4(0.f, 0.f, 0.f, 0.f);
            Bs[kq * 4 + 0][row] = b.x; Bs[kq * 4 + 1][row] = b.y;
            Bs[kq * 4 + 2][row] = b.z; Bs[kq * 4 + 3][row] = b.w;
        }
        __syncthreads();

#pragma unroll
        for (int k = 0; k < BK; k++) {
            float4 av4[TM / 4];
            float4 bv4[TN / 4];
#pragma unroll
            for (int q = 0; q < TM / 4; q++)
                av4[q] = *reinterpret_cast<const float4*>(&As[k][ty * TM + q * 4]);
#pragma unroll
            for (int q = 0; q < TN / 4; q++)
                bv4[q] = *reinterpret_cast<const float4*>(&Bs[k][tx * TN + q * 4]);
            const float* av = reinterpret_cast<const float*>(av4);
            const float* bv = reinterpret_cast<const float*>(bv4);
#pragma unroll
            for (int i = 0; i < TM; i++)
#pragma unroll
                for (int j = 0; j < TN; j++)
                    acc[i][j] = fmaf(av[i], bv[j], acc[i][j]);
        }
        __syncthreads();
    }

    if constexpr (!FUSED) {
#pragma unroll
        for (int i = 0; i < TM; i++) {
            int m = m0 + ty * TM + i;
            if (m >= M) continue;
#pragma unroll
            for (int j = 0; j < TN; j++) {
                int n = n0 + tx * TN + j;
                if (n >= N) continue;
                float r = acc[i][j];
                if (bias1) r += bias1[n];
                if (bias2) r += bias2[n];
                if (accC)  r += C[(size_t)m * ldc + n];
                C[(size_t)m * ldc + n] = r;
            }
        }
    } else {
        // TX must be 16 so each row's partial lives in a contiguous 16-lane group.
#pragma unroll
        for (int i = 0; i < TM; i++) {
            int m = m0 + ty * TM + i;
            int b = m & (BATCH - 1);
            float p = 0.f;
#pragma unroll
            for (int j = 0; j < TN; j++) {
                int n   = n0 + tx * TN + j;
                float e = tanhf(acc[i][j] + qadd[b * HDIM + n] + bias1[n]);
                p = fmaf(e, vvec[n], p);
            }
            p += __shfl_xor_sync(0xffffffffu, p, 1);
            p += __shfl_xor_sync(0xffffffffu, p, 2);
            p += __shfl_xor_sync(0xffffffffu, p, 4);
            p += __shfl_xor_sync(0xffffffffu, p, 8);
            if (tx == 0 && m < M)
                part[(size_t)m * gridDim.x + blockIdx.x] = p;
        }
    }
}

// ---------------------------------------------------------------------------
// Small helper kernels
// ---------------------------------------------------------------------------
__global__ void gather_embed(const int* __restrict__ idx,
                             const float* __restrict__ embed,
                             float* __restrict__ xcat)
{
    int b = blockIdx.x, e = threadIdx.x;              // 512 threads
    xcat[b * 1536 + e] = embed[(size_t)idx[b] * EDIM + e];
}

__global__ void copy_hlast(const float* __restrict__ h0, float* __restrict__ docq)
{
    int b = blockIdx.x, h = threadIdx.x;              // 1024 threads
    docq[b * 2048 + h] = h0[b * HDIM + h];
}

__global__ void qsoftmax(const float* __restrict__ part, float* __restrict__ w)
{
    int b = blockIdx.x, t = threadIdx.x;              // 32 threads
    const float* p = part + ((size_t)t * BATCH + b) * 8;
    float s = p[0] + p[1] + p[2] + p[3] + p[4] + p[5] + p[6] + p[7];
    float mx = s;
#pragma unroll
    for (int o = 16; o; o >>= 1) mx = fmaxf(mx, __shfl_xor_sync(0xffffffffu, mx, o));
    float e = expf(s - mx);
    float sum = e;
#pragma unroll
    for (int o = 16; o; o >>= 1) sum += __shfl_xor_sync(0xffffffffu, sum, o);
    w[b * LQ + t] = e / sum;
}

__global__ void dsoftmax(const float* __restrict__ part,
                         float* __restrict__ w, float* __restrict__ outw)
{
    __shared__ float sh[256];
    int b = blockIdx.x, tid = threadIdx.x;            // 256 threads
    float mx = -1e30f;
    for (int t = tid; t < LD; t += 256) {
        const float* p = part + ((size_t)t * BATCH + b) * 8;
        float s = p[0] + p[1] + p[2] + p[3] + p[4] + p[5] + p[6] + p[7];
        mx = fmaxf(mx, s);
    }
    sh[tid] = mx; __syncthreads();
    for (int s = 128; s > 0; s >>= 1) { if (tid < s) sh[tid] = fmaxf(sh[tid], sh[tid + s]); __syncthreads(); }
    mx = sh[0]; __syncthreads();

    float sum = 0.f;
    for (int t = tid; t < LD; t += 256) {
        const float* p = part + ((size_t)t * BATCH + b) * 8;
        float s = p[0] + p[1] + p[2] + p[3] + p[4] + p[5] + p[6] + p[7];
        sum += expf(s - mx);
    }
    sh[tid] = sum; __syncthreads();
    for (int s = 128; s > 0; s >>= 1) { if (tid < s) sh[tid] += sh[tid + s]; __syncthreads(); }
    float tot = sh[0];

    for (int t = tid; t < LD; t += 256) {
        const float* p = part + ((size_t)t * BATCH + b) * 8;
        float s = p[0] + p[1] + p[2] + p[3] + p[4] + p[5] + p[6] + p[7];
        float v = expf(s - mx) / tot;
        w[b * LD + t]    = v;
        outw[b * LD + t] = v;
    }
}

// ctx[b,h] = sum_t w[b,t] * enc[t,b,h]; written to up to two destinations
__global__ void weighted_ctx(const float* __restrict__ w, int T,
                             const float* __restrict__ enc,
                             float* __restrict__ dst1, int ld1, int off1,
                             float* __restrict__ dst2, int ld2, int off2)
{
    int b = blockIdx.y;
    int h = blockIdx.x * blockDim.x + threadIdx.x;
    const float* wb = w + b * T;
    float a = 0.f;
    for (int t = 0; t < T; t++)
        a = fmaf(wb[t], enc[((size_t)t * BATCH + b) * HDIM + h], a);
    dst1[(size_t)b * ld1 + off1 + h] = a;
    if (dst2) dst2[(size_t)b * ld2 + off2 + h] = a;
}

__device__ __forceinline__ float sigf(float x) { return 1.f / (1.f + expf(-x)); }

__global__ void lstm_cell(const float* __restrict__ gates,
                          const float* __restrict__ cprev,
                          float* __restrict__ hout, float* __restrict__ cout,
                          float* __restrict__ hout2)   // optional, ld=2048 off=0
{
    int idx = blockIdx.x * blockDim.x + threadIdx.x;  // B*H
    int b = idx >> 10, h = idx & 1023;
    const float* g = gates + b * 4096;
    float i  = sigf(g[h]);
    float f  = sigf(g[1024 + h]);
    float gg = tanhf(g[2048 + h]);
    float o  = sigf(g[3072 + h]);
    float c  = f * cprev[idx] + i * gg;
    float hh = o * tanhf(c);
    hout[idx] = hh;
    cout[idx] = c;
    if (hout2) hout2[b * 2048 + h] = hh;
}

__global__ void logsoftmax_rows(float* __restrict__ x)
{
    __shared__ float sh[512];
    int b = blockIdx.x, tid = threadIdx.x;            // 512 threads
    float* row = x + (size_t)b * VDIM;

    float mx = -1e30f;
    for (int i = tid; i < VDIM; i += 512) mx = fmaxf(mx, row[i]);
    sh[tid] = mx; __syncthreads();
    for (int s = 256; s > 0; s >>= 1) { if (tid < s) sh[tid] = fmaxf(sh[tid], sh[tid + s]); __syncthreads(); }
    mx = sh[0]; __syncthreads();

    float sum = 0.f;
    for (int i = tid; i < VDIM; i += 512) sum += expf(row[i] - mx);
    sh[tid] = sum; __syncthreads();
    for (int s = 256; s > 0; s >>= 1) { if (tid < s) sh[tid] += sh[tid + s]; __syncthreads(); }
    float lse = mx + logf(sh[0]);

    for (int i = tid; i < VDIM; i += 512) row[i] -= lse;
}

// ---------------------------------------------------------------------------
// Launcher
// ---------------------------------------------------------------------------
extern "C" void kernel_launch(void* const* d_in, const int* in_sizes, int n_in,
                              void* d_out, int out_size)
{
    (void)in_sizes; (void)n_in; (void)out_size;
    const int*   input = (const int*)  d_in[0];
    const float* h0    = (const float*)d_in[1];
    const float* c0    = (const float*)d_in[2];
    const float* dh0   = (const float*)d_in[3];
    const float* dc0   = (const float*)d_in[4];
    const float* qo    = (const float*)d_in[5];
    const float* enc   = (const float*)d_in[6];
    const float* embed = (const float*)d_in[7];
    const float* W_qa  = (const float*)d_in[8];
    const float* b_qa  = (const float*)d_in[9];
    const float* v_q   = (const float*)d_in[10];
    const float* W_da  = (const float*)d_in[11];
    const float* b_da  = (const float*)d_in[12];
    const float* v_d   = (const float*)d_in[13];
    const float* W_ih  = (const float*)d_in[14];
    const float* W_hh  = (const float*)d_in[15];
    const float* b_ih  = (const float*)d_in[16];
    const float* b_hh  = (const float*)d_in[17];
    const float* Wd_ih = (const float*)d_in[18];
    const float* Wd_hh = (const float*)d_in[19];
    const float* bd_ih = (const float*)d_in[20];
    const float* bd_hh = (const float*)d_in[21];
    const float* W_out = (const float*)d_in[22];
    const float* b_out = (const float*)d_in[23];
    float* out = (float*)d_out;

    float *qpart, *partq, *wq, *docq, *dqpart, *partd, *wd, *xcat, *xout, *gates, *dgates;
    cudaGetSymbolAddress((void**)&qpart,  g_qpart);
    cudaGetSymbolAddress((void**)&partq,  g_partq);
    cudaGetSymbolAddress((void**)&wq,     g_wq);
    cudaGetSymbolAddress((void**)&docq,   g_docq);
    cudaGetSymbolAddress((void**)&dqpart, g_dqpart);
    cudaGetSymbolAddress((void**)&partd,  g_partd);
    cudaGetSymbolAddress((void**)&wd,     g_wd);
    cudaGetSymbolAddress((void**)&xcat,   g_xcat);
    cudaGetSymbolAddress((void**)&xout,   g_xout);
    cudaGetSymbolAddress((void**)&gates,  g_gates);
    cudaGetSymbolAddress((void**)&dgates, g_dgates);

    // Embedding gather into xcat[:, 0:512]; docq[:, 0:1024] = h_last
    gather_embed<<<BATCH, 512>>>(input, embed, xcat);
    copy_hlast  <<<BATCH, 1024>>>(h0, docq);

    // ---- Query attention ----
    // qpart = h_last @ W_qa[:, :H]^T
    gemm_nt<64,128,16,4,8,false><<<dim3(8,1),256>>>(
        h0, HDIM, W_qa, 2*HDIM, qpart, HDIM, BATCH, HDIM, HDIM,
        nullptr, nullptr, 0, nullptr, nullptr, nullptr);
    // fused energy + score partials over query_outputs
    gemm_nt<128,128,16,8,8,true><<<dim3(8, LQ*BATCH/128),256>>>(
        qo, HDIM, W_qa + HDIM, 2*HDIM, nullptr, 0, LQ*BATCH, HDIM, HDIM,
        b_qa, nullptr, 0, qpart, v_q, partq);
    qsoftmax<<<BATCH, 32>>>(partq, wq);
    weighted_ctx<<<dim3(HDIM/256, BATCH), 256>>>(wq, LQ, qo,
        docq, 2048, 1024, nullptr, 0, 0);

    // ---- Doc attention ----
    // dqpart = [h_last | q_ctx] @ W_da[:, :2H]^T
    gemm_nt<64,128,16,4,8,false><<<dim3(8,1),256>>>(
        docq, 2048, W_da, 3*HDIM, dqpart, HDIM, BATCH, HDIM, 2*HDIM,
        nullptr, nullptr, 0, nullptr, nullptr, nullptr);
    gemm_nt<128,128,16,8,8,true><<<dim3(8, LD*BATCH/128),256>>>(
        enc, HDIM, W_da + 2*HDIM, 3*HDIM, nullptr, 0, LD*BATCH, HDIM, HDIM,
        b_da, nullptr, 0, dqpart, v_d, partd);
    dsoftmax<<<BATCH, 256>>>(partd, wd, out + OFF_DOCW);
    weighted_ctx<<<dim3(HDIM/256, BATCH), 256>>>(wd, LD, enc,
        xcat, 1536, 512, xout, 2048, 1024);

    // ---- Distraction LSTM: dgates = doc_ctx@Wd_ih^T + dh0@Wd_hh^T + biases ----
    gemm_nt<64,128,16,4,8,false><<<dim3(32,1),256>>>(
        xcat + 512, 1536, Wd_ih, HDIM, dgates, 4096, BATCH, 4096, HDIM,
        nullptr, nullptr, 0, nullptr, nullptr, nullptr);
    gemm_nt<64,128,16,4,8,false><<<dim3(32,1),256>>>(
        dh0, HDIM, Wd_hh, HDIM, dgates, 4096, BATCH, 4096, HDIM,
        bd_ih, bd_hh, 1, nullptr, nullptr, nullptr);
    lstm_cell<<<BATCH*HDIM/256, 256>>>(dgates, dc0, out + OFF_DH, out + OFF_DC, nullptr);

    // ---- Main LSTM: gates = [emb|doc_ctx]@W_ih^T + h0@W_hh^T + biases ----
    gemm_nt<64,128,16,4,8,false><<<dim3(32,1),256>>>(
        xcat, 1536, W_ih, 1536, gates, 4096, BATCH, 4096, 1536,
        nullptr, nullptr, 0, nullptr, nullptr, nullptr);
    gemm_nt<64,128,16,4,8,false><<<dim3(32,1),256>>>(
        h0, HDIM, W_hh, HDIM, gates, 4096, BATCH, 4096, HDIM,
        b_ih, b_hh, 1, nullptr, nullptr, nullptr);
    lstm_cell<<<BATCH*HDIM/256, 256>>>(gates, c0, out + OFF_H1, out + OFF_C1, xout);

    // ---- Output projection + log_softmax ----
    gemm_nt<64,128,16,4,8,false><<<dim3((VDIM+127)/128, 1),256>>>(
        xout, 2048, W_out, 2048, out, VDIM, BATCH, VDIM, 2048,
        b_out, nullptr, 0, nullptr, nullptr, nullptr);
    logsoftmax_rows<<<BATCH, 512>>>(out);
}

// round 7
// speedup vs baseline: 1.0008x; 1.0008x over previous
#include <cuda_runtime.h>
#include <math.h>

// ---------------------------------------------------------------------------
// Problem constants
// ---------------------------------------------------------------------------
#define BATCH 64
#define HDIM  1024
#define EDIM  512
#define VDIM  50000
#define LQ    32
#define LD    400

// Output layout (tuple concat, float32):
// out[B,V], h1[1,B,H], c1, dh, dc, doc_w[B,1,LD]
#define OFF_OUT   0
#define OFF_H1    (3200000)
#define OFF_C1    (OFF_H1 + 65536)
#define OFF_DH    (OFF_C1 + 65536)
#define OFF_DC    (OFF_DH + 65536)
#define OFF_DOCW  (OFF_DC + 65536)

// ---------------------------------------------------------------------------
// Scratch (device globals: no allocations allowed)
// ---------------------------------------------------------------------------
__device__ float g_qpart [BATCH * HDIM];          // h_last @ W_qa_h^T
__device__ float g_partq [LQ * BATCH * 8];        // query score partials (8 n-blocks)
__device__ float g_wq    [BATCH * LQ];            // query attn weights
__device__ float g_docq  [BATCH * 2 * HDIM];      // [h_last | q_ctx]
__device__ float g_dqpart[BATCH * HDIM];          // doc_query @ W_da_h^T
__device__ float g_partd [LD * BATCH * 8];        // doc score partials
__device__ float g_wd    [BATCH * LD];            // doc attn weights
__device__ float g_xcat  [BATCH * 1536];          // [embedded(512) | doc_ctx(1024)]
__device__ float g_xout  [BATCH * 2048];          // [h1 | doc_ctx]
__device__ float g_gates [BATCH * 4096];
__device__ float g_dgates[BATCH * 4096];

// ---------------------------------------------------------------------------
// Generic NT SGEMM: C[M,N] = A[M,K] * W[N,K]^T  (both K-contiguous)
// FUSED=false : C = acc (+bias1[n]) (+bias2[n]) (+= C if accC)
// FUSED=true  : per-row partial of  sum_n tanh(acc + qadd[b,n] + bias1[n])*v[n]
//               written deterministically to part[m*gridDim.x + blockIdx.x]
//               (b = m % 64; requires N-tiles exactly covering N=1024, BN/TN==16)
// ---------------------------------------------------------------------------
template<int BM, int BN, int BK, int TM, int TN, bool FUSED>
__global__ __launch_bounds__((BM/TM)*(BN/TN))
void gemm_nt(const float* __restrict__ A, int lda,
             const float* __restrict__ W, int ldw,
             float* __restrict__ C, int ldc,
             int M, int N, int K,
             const float* __restrict__ bias1,
             const float* __restrict__ bias2,
             int accC,
             const float* __restrict__ qadd,
             const float* __restrict__ vvec,
             float* __restrict__ part)
{
    constexpr int NTH = (BM / TM) * (BN / TN);
    constexpr int TX  = BN / TN;
    __shared__ float As[BK][BM];
    __shared__ float Bs[BK][BN];

    const int tid = threadIdx.x;
    const int tx  = tid % TX;
    const int ty  = tid / TX;
    const int m0  = blockIdx.y * BM;
    const int n0  = blockIdx.x * BN;

    float acc[TM][TN];
#pragma unroll
    for (int i = 0; i < TM; i++)
#pragma unroll
        for (int j = 0; j < TN; j++) acc[i][j] = 0.f;

    constexpr int LA = (BM * BK / 4) / NTH;
    constexpr int LB = (BN * BK / 4) / NTH;

    for (int k0 = 0; k0 < K; k0 += BK) {
#pragma unroll
        for (int i = 0; i < LA; i++) {
            int s   = i * NTH + tid;
            int row = s / (BK / 4);
            int kq  = s % (BK / 4);
            float4 a;
            if (m0 + row < M)
                a = *reinterpret_cast<const float4*>(A + (size_t)(m0 + row) * lda + k0 + kq * 4);
            else
                a = make_float4(0.f, 0.f, 0.f, 0.f);
            As[kq * 4 + 0][row] = a.x; As[kq * 4 + 1][row] = a.y;
            As[kq * 4 + 2][row] = a.z; As[kq * 4 + 3][row] = a.w;
        }
#pragma unroll
        for (int i = 0; i < LB; i++) {
            int s   = i * NTH + tid;
            int row = s / (BK / 4);
            int kq  = s % (BK / 4);
            float4 b;
            if (n0 + row < N)
                b = *reinterpret_cast<const float4*>(W + (size_t)(n0 + row) * ldw + k0 + kq * 4);
            else
                b = make_float4(0.f, 0.f, 0.f, 0.f);
            Bs[kq * 4 + 0][row] = b.x; Bs[kq * 4 + 1][row] = b.y;
            Bs[kq * 4 + 2][row] = b.z; Bs[kq * 4 + 3][row] = b.w;
        }
        __syncthreads();

#pragma unroll
        for (int k = 0; k < BK; k++) {
            float4 av4[TM / 4];
            float4 bv4[TN / 4];
#pragma unroll
            for (int q = 0; q < TM / 4; q++)
                av4[q] = *reinterpret_cast<const float4*>(&As[k][ty * TM + q * 4]);
#pragma unroll
            for (int q = 0; q < TN / 4; q++)
                bv4[q] = *reinterpret_cast<const float4*>(&Bs[k][tx * TN + q * 4]);
            const float* av = reinterpret_cast<const float*>(av4);
            const float* bv = reinterpret_cast<const float*>(bv4);
#pragma unroll
            for (int i = 0; i < TM; i++)
#pragma unroll
                for (int j = 0; j < TN; j++)
                    acc[i][j] = fmaf(av[i], bv[j], acc[i][j]);
        }
        __syncthreads();
    }

    if constexpr (!FUSED) {
#pragma unroll
        for (int i = 0; i < TM; i++) {
            int m = m0 + ty * TM + i;
            if (m >= M) continue;
#pragma unroll
            for (int j = 0; j < TN; j++) {
                int n = n0 + tx * TN + j;
                if (n >= N) continue;
                float r = acc[i][j];
                if (bias1) r += bias1[n];
                if (bias2) r += bias2[n];
                if (accC)  r += C[(size_t)m * ldc + n];
                C[(size_t)m * ldc + n] = r;
            }
        }
    } else {
        // TX must be 16 so each row's partial lives in a contiguous 16-lane group.
#pragma unroll
        for (int i = 0; i < TM; i++) {
            int m = m0 + ty * TM + i;
            int b = m & (BATCH - 1);
            float p = 0.f;
#pragma unroll
            for (int j = 0; j < TN; j++) {
                int n   = n0 + tx * TN + j;
                float e = tanhf(acc[i][j] + qadd[b * HDIM + n] + bias1[n]);
                p = fmaf(e, vvec[n], p);
            }
            p += __shfl_xor_sync(0xffffffffu, p, 1);
            p += __shfl_xor_sync(0xffffffffu, p, 2);
            p += __shfl_xor_sync(0xffffffffu, p, 4);
            p += __shfl_xor_sync(0xffffffffu, p, 8);
            if (tx == 0 && m < M)
                part[(size_t)m * gridDim.x + blockIdx.x] = p;
        }
    }
}

// ---------------------------------------------------------------------------
// Small helper kernels
// ---------------------------------------------------------------------------
__global__ void gather_embed(const int* __restrict__ idx,
                             const float* __restrict__ embed,
                             float* __restrict__ xcat)
{
    int b = blockIdx.x, e = threadIdx.x;              // 512 threads
    xcat[b * 1536 + e] = embed[(size_t)idx[b] * EDIM + e];
}

__global__ void copy_hlast(const float* __restrict__ h0, float* __restrict__ docq)
{
    int b = blockIdx.x, h = threadIdx.x;              // 1024 threads
    docq[b * 2048 + h] = h0[b * HDIM + h];
}

__global__ void qsoftmax(const float* __restrict__ part, float* __restrict__ w)
{
    int b = blockIdx.x, t = threadIdx.x;              // 32 threads
    const float* p = part + ((size_t)t * BATCH + b) * 8;
    float s = p[0] + p[1] + p[2] + p[3] + p[4] + p[5] + p[6] + p[7];
    float mx = s;
#pragma unroll
    for (int o = 16; o; o >>= 1) mx = fmaxf(mx, __shfl_xor_sync(0xffffffffu, mx, o));
    float e = expf(s - mx);
    float sum = e;
#pragma unroll
    for (int o = 16; o; o >>= 1) sum += __shfl_xor_sync(0xffffffffu, sum, o);
    w[b * LQ + t] = e / sum;
}

__global__ void dsoftmax(const float* __restrict__ part,
                         float* __restrict__ w, float* __restrict__ outw)
{
    __shared__ float sh[256];
    int b = blockIdx.x, tid = threadIdx.x;            // 256 threads
    float mx = -1e30f;
    for (int t = tid; t < LD; t += 256) {
        const float* p = part + ((size_t)t * BATCH + b) * 8;
        float s = p[0] + p[1] + p[2] + p[3] + p[4] + p[5] + p[6] + p[7];
        mx = fmaxf(mx, s);
    }
    sh[tid] = mx; __syncthreads();
    for (int s = 128; s > 0; s >>= 1) { if (tid < s) sh[tid] = fmaxf(sh[tid], sh[tid + s]); __syncthreads(); }
    mx = sh[0]; __syncthreads();

    float sum = 0.f;
    for (int t = tid; t < LD; t += 256) {
        const float* p = part + ((size_t)t * BATCH + b) * 8;
        float s = p[0] + p[1] + p[2] + p[3] + p[4] + p[5] + p[6] + p[7];
        sum += expf(s - mx);
    }
    sh[tid] = sum; __syncthreads();
    for (int s = 128; s > 0; s >>= 1) { if (tid < s) sh[tid] += sh[tid + s]; __syncthreads(); }
    float tot = sh[0];

    for (int t = tid; t < LD; t += 256) {
        const float* p = part + ((size_t)t * BATCH + b) * 8;
        float s = p[0] + p[1] + p[2] + p[3] + p[4] + p[5] + p[6] + p[7];
        float v = expf(s - mx) / tot;
        w[b * LD + t]    = v;
        outw[b * LD + t] = v;
    }
}

// ctx[b,h] = sum_t w[b,t] * enc[t,b,h]; written to up to two destinations
__global__ void weighted_ctx(const float* __restrict__ w, int T,
                             const float* __restrict__ enc,
                             float* __restrict__ dst1, int ld1, int off1,
                             float* __restrict__ dst2, int ld2, int off2)
{
    int b = blockIdx.y;
    int h = blockIdx.x * blockDim.x + threadIdx.x;
    const float* wb = w + b * T;
    float a = 0.f;
    for (int t = 0; t < T; t++)
        a = fmaf(wb[t], enc[((size_t)t * BATCH + b) * HDIM + h], a);
    dst1[(size_t)b * ld1 + off1 + h] = a;
    if (dst2) dst2[(size_t)b * ld2 + off2 + h] = a;
}

__device__ __forceinline__ float sigf(float x) { return 1.f / (1.f + expf(-x)); }

__global__ void lstm_cell(const float* __restrict__ gates,
                          const float* __restrict__ cprev,
                          float* __restrict__ hout, float* __restrict__ cout,
                          float* __restrict__ hout2)   // optional, ld=2048 off=0
{
    int idx = blockIdx.x * blockDim.x + threadIdx.x;  // B*H
    int b = idx >> 10, h = idx & 1023;
    const float* g = gates + b * 4096;
    float i  = sigf(g[h]);
    float f  = sigf(g[1024 + h]);
    float gg = tanhf(g[2048 + h]);
    float o  = sigf(g[3072 + h]);
    float c  = f * cprev[idx] + i * gg;
    float hh = o * tanhf(c);
    hout[idx] = hh;
    cout[idx] = c;
    if (hout2) hout2[b * 2048 + h] = hh;
}

__global__ void logsoftmax_rows(float* __restrict__ x)
{
    __shared__ float sh[512];
    int b = blockIdx.x, tid = threadIdx.x;            // 512 threads
    float* row = x + (size_t)b * VDIM;

    float mx = -1e30f;
    for (int i = tid; i < VDIM; i += 512) mx = fmaxf(mx, row[i]);
    sh[tid] = mx; __syncthreads();
    for (int s = 256; s > 0; s >>= 1) { if (tid < s) sh[tid] = fmaxf(sh[tid], sh[tid + s]); __syncthreads(); }
    mx = sh[0]; __syncthreads();

    float sum = 0.f;
    for (int i = tid; i < VDIM; i += 512) sum += expf(row[i] - mx);
    sh[tid] = sum; __syncthreads();
    for (int s = 256; s > 0; s >>= 1) { if (tid < s) sh[tid] += sh[tid + s]; __syncthreads(); }
    float lse = mx + logf(sh[0]);

    for (int i = tid; i < VDIM; i += 512) row[i] -= lse;
}

// ---------------------------------------------------------------------------
// Launcher
// ---------------------------------------------------------------------------
extern "C" void kernel_launch(void* const* d_in, const int* in_sizes, int n_in,
                              void* d_out, int out_size)
{
    (void)in_sizes; (void)n_in; (void)out_size;
    const int*   input = (const int*)  d_in[0];
    const float* h0    = (const float*)d_in[1];
    const float* c0    = (const float*)d_in[2];
    const float* dh0   = (const float*)d_in[3];
    const float* dc0   = (const float*)d_in[4];
    const float* qo    = (const float*)d_in[5];
    const float* enc   = (const float*)d_in[6];
    const float* embed = (const float*)d_in[7];
    const float* W_qa  = (const float*)d_in[8];
    const float* b_qa  = (const float*)d_in[9];
    const float* v_q   = (const float*)d_in[10];
    const float* W_da  = (const float*)d_in[11];
    const float* b_da  = (const float*)d_in[12];
    const float* v_d   = (const float*)d_in[13];
    const float* W_ih  = (const float*)d_in[14];
    const float* W_hh  = (const float*)d_in[15];
    const float* b_ih  = (const float*)d_in[16];
    const float* b_hh  = (const float*)d_in[17];
    const float* Wd_ih = (const float*)d_in[18];
    const float* Wd_hh = (const float*)d_in[19];
    const float* bd_ih = (const float*)d_in[20];
    const float* bd_hh = (const float*)d_in[21];
    const float* W_out = (const float*)d_in[22];
    const float* b_out = (const float*)d_in[23];
    float* out = (float*)d_out;

    float *qpart, *partq, *wq, *docq, *dqpart, *partd, *wd, *xcat, *xout, *gates, *dgates;
    cudaGetSymbolAddress((void**)&qpart,  g_qpart);
    cudaGetSymbolAddress((void**)&partq,  g_partq);
    cudaGetSymbolAddress((void**)&wq,     g_wq);
    cudaGetSymbolAddress((void**)&docq,   g_docq);
    cudaGetSymbolAddress((void**)&dqpart, g_dqpart);
    cudaGetSymbolAddress((void**)&partd,  g_partd);
    cudaGetSymbolAddress((void**)&wd,     g_wd);
    cudaGetSymbolAddress((void**)&xcat,   g_xcat);
    cudaGetSymbolAddress((void**)&xout,   g_xout);
    cudaGetSymbolAddress((void**)&gates,  g_gates);
    cudaGetSymbolAddress((void**)&dgates, g_dgates);

    // Embedding gather into xcat[:, 0:512]; docq[:, 0:1024] = h_last
    gather_embed<<<BATCH, 512>>>(input, embed, xcat);
    copy_hlast  <<<BATCH, 1024>>>(h0, docq);

    // ---- Query attention ----
    // qpart = h_last @ W_qa[:, :H]^T
    gemm_nt<64,128,16,4,8,false><<<dim3(8,1),256>>>(
        h0, HDIM, W_qa, 2*HDIM, qpart, HDIM, BATCH, HDIM, HDIM,
        nullptr, nullptr, 0, nullptr, nullptr, nullptr);
    // fused energy + score partials over query_outputs
    gemm_nt<128,128,16,8,8,true><<<dim3(8, LQ*BATCH/128),256>>>(
        qo, HDIM, W_qa + HDIM, 2*HDIM, nullptr, 0, LQ*BATCH, HDIM, HDIM,
        b_qa, nullptr, 0, qpart, v_q, partq);
    qsoftmax<<<BATCH, 32>>>(partq, wq);
    weighted_ctx<<<dim3(HDIM/256, BATCH), 256>>>(wq, LQ, qo,
        docq, 2048, 1024, nullptr, 0, 0);

    // ---- Doc attention ----
    // dqpart = [h_last | q_ctx] @ W_da[:, :2H]^T
    gemm_nt<64,128,16,4,8,false><<<dim3(8,1),256>>>(
        docq, 2048, W_da, 3*HDIM, dqpart, HDIM, BATCH, HDIM, 2*HDIM,
        nullptr, nullptr, 0, nullptr, nullptr, nullptr);
    gemm_nt<128,128,16,8,8,true><<<dim3(8, LD*BATCH/128),256>>>(
        enc, HDIM, W_da + 2*HDIM, 3*HDIM, nullptr, 0, LD*BATCH, HDIM, HDIM,
        b_da, nullptr, 0, dqpart, v_d, partd);
    dsoftmax<<<BATCH, 256>>>(partd, wd, out + OFF_DOCW);
    weighted_ctx<<<dim3(HDIM/256, BATCH), 256>>>(wd, LD, enc,
        xcat, 1536, 512, xout, 2048, 1024);

    // ---- Distraction LSTM: dgates = doc_ctx@Wd_ih^T + dh0@Wd_hh^T + biases ----
    gemm_nt<64,128,16,4,8,false><<<dim3(32,1),256>>>(
        xcat + 512, 1536, Wd_ih, HDIM, dgates, 4096, BATCH, 4096, HDIM,
        nullptr, nullptr, 0, nullptr, nullptr, nullptr);
    gemm_nt<64,128,16,4,8,false><<<dim3(32,1),256>>>(
        dh0, HDIM, Wd_hh, HDIM, dgates, 4096, BATCH, 4096, HDIM,
        bd_ih, bd_hh, 1, nullptr, nullptr, nullptr);
    lstm_cell<<<BATCH*HDIM/256, 256>>>(dgates, dc0, out + OFF_DH, out + OFF_DC, nullptr);

    // ---- Main LSTM: gates = [emb|doc_ctx]@W_ih^T + h0@W_hh^T + biases ----
    gemm_nt<64,128,16,4,8,false><<<dim3(32,1),256>>>(
        xcat, 1536, W_ih, 1536, gates, 4096, BATCH, 4096, 1536,
        nullptr, nullptr, 0, nullptr, nullptr, nullptr);
    gemm_nt<64,128,16,4,8,false><<<dim3(32,1),256>>>(
        h0, HDIM, W_hh, HDIM, gates, 4096, BATCH, 4096, HDIM,
        b_ih, b_hh, 1, nullptr, nullptr, nullptr);
    lstm_cell<<<BATCH*HDIM/256, 256>>>(gates, c0, out + OFF_H1, out + OFF_C1, xout);

    // ---- Output projection + log_softmax ----
    gemm_nt<64,128,16,4,8,false><<<dim3((VDIM+127)/128, 1),256>>>(
        xout, 2048, W_out, 2048, out, VDIM, BATCH, VDIM, 2048,
        b_out, nullptr, 0, nullptr, nullptr, nullptr);
    logsoftmax_rows<<<BATCH, 512>>>(out);
}